// round 1
// baseline (speedup 1.0000x reference)
#include <cuda_runtime.h>
#include <cuda_bf16.h>
#include <math.h>

// Problem constants
#define T_STEPS 16384
#define D_IN    257
#define H_DIM   512
#define G4H     2048   // 4*H
#define O_DIM   257
#define REC_CTAS 128   // recurrence CTAs; each owns 4 hidden units (16 gate rows)

// Scratch (static __device__ arrays — no allocation allowed)
__device__ float    g_xg[(size_t)T_STEPS * G4H];   // 128 MB: precomputed input gates + biases
__device__ float    g_hs[(size_t)T_STEPS * H_DIM]; // 32 MB: h per timestep
__device__ float    g_hbuf[2 * H_DIM];             // double-buffered h exchange
__device__ unsigned g_stamp[REC_CTAS * 8];         // per-CTA step stamps, 32B strided

// ---------------------------------------------------------------------------
// init: reset stamps each launch (monotonic within a launch, must restart at 0)
// ---------------------------------------------------------------------------
__global__ void init_kernel() {
    int tid = threadIdx.x;
    for (int i = tid; i < REC_CTAS * 8; i += 256) g_stamp[i] = 0u;
}

// ---------------------------------------------------------------------------
// Kernel A: x_gates[T, 4H] = stft @ W_ih^T + (b_ih + b_hh)
// CTA = 16 t-rows, 256 threads, each thread one output column per col-group.
// stft tile broadcast from smem (float4), W rows streamed per-thread (L1-friendly).
// ---------------------------------------------------------------------------
__global__ void __launch_bounds__(256) xgate_gemm(
    const float* __restrict__ stft, const float* __restrict__ W_ih,
    const float* __restrict__ b_ih, const float* __restrict__ b_hh)
{
    __shared__ float s_sh[16 * 260];  // row stride 260 (mult of 4 for float4)
    const int tid = threadIdx.x;
    const int t0  = blockIdx.x * 16;

    for (int r = 0; r < 16; r++)
        for (int d = tid; d < D_IN; d += 256)
            s_sh[r * 260 + d] = stft[(size_t)(t0 + r) * D_IN + d];
    __syncthreads();

    for (int cg = 0; cg < 8; cg++) {
        const int c = cg * 256 + tid;                  // 0..2047
        const float* wrow = W_ih + (size_t)c * D_IN;
        float acc[16];
        #pragma unroll
        for (int r = 0; r < 16; r++) acc[r] = 0.f;

        for (int dd = 0; dd < 64; dd++) {              // 64*4 = 256 of 257
            const float w0 = __ldg(wrow + dd * 4 + 0);
            const float w1 = __ldg(wrow + dd * 4 + 1);
            const float w2 = __ldg(wrow + dd * 4 + 2);
            const float w3 = __ldg(wrow + dd * 4 + 3);
            #pragma unroll
            for (int r = 0; r < 16; r++) {
                const float4 s4 = *reinterpret_cast<const float4*>(&s_sh[r * 260 + dd * 4]);
                float a = acc[r];
                a = fmaf(w0, s4.x, a);
                a = fmaf(w1, s4.y, a);
                a = fmaf(w2, s4.z, a);
                a = fmaf(w3, s4.w, a);
                acc[r] = a;
            }
        }
        const float wl = __ldg(wrow + 256);            // remainder d = 256
        #pragma unroll
        for (int r = 0; r < 16; r++) acc[r] = fmaf(wl, s_sh[r * 260 + 256], acc[r]);

        const float bias = __ldg(b_ih + c) + __ldg(b_hh + c);
        #pragma unroll
        for (int r = 0; r < 16; r++)
            g_xg[(size_t)(t0 + r) * G4H + c] = acc[r] + bias;
    }
}

// ---------------------------------------------------------------------------
// Kernel B: sequential LSTM recurrence, persistent grid of 128 CTAs.
// CTA b owns hidden units u0=4b..4b+3 -> 16 gate rows (i,f,g,o x 4 units).
// W_hh slice lives in registers (32 floats/thread). h broadcast via L2 with
// per-CTA monotonic stamps (release store / acquire poll), double-buffered.
// Thread mapping: warp w(0..7), lane l: row r=l&15, kg=w*2+(l>>4) (16 k-groups of 32).
// ---------------------------------------------------------------------------
__device__ __forceinline__ float fsigm(float x) { return 1.0f / (1.0f + __expf(-x)); }
__device__ __forceinline__ float ftanh(float x) { return 2.0f / (1.0f + __expf(-2.0f * x)) - 1.0f; }

__global__ void __launch_bounds__(256) lstm_rec(const float* __restrict__ W_hh)
{
    __shared__ float4 h4[144];   // padded: index kg*9 + i (conflict-free)
    __shared__ float  red[128];  // per-warp row partials
    __shared__ float  gv[16];    // final gate preactivations

    const int tid = threadIdx.x;
    const int b   = blockIdx.x;
    const int w   = tid >> 5;
    const int l   = tid & 31;
    const int r   = l & 15;
    const int kh  = l >> 4;
    const int kg  = w * 2 + kh;          // 0..15, k range [kg*32, kg*32+32)
    const int u0  = b * 4;
    const int rowg = (r >> 2) * 512 + u0 + (r & 3);  // global gate row

    // weights for (rowg, k in [kg*32, kg*32+32)) in registers
    float4 wv[8];
    const float4* wp = reinterpret_cast<const float4*>(W_hh + (size_t)rowg * H_DIM + (size_t)kg * 32);
    #pragma unroll
    for (int i = 0; i < 8; i++) wv[i] = __ldg(wp + i);

    if (tid < 128) h4[(tid >> 3) * 9 + (tid & 7)] = make_float4(0.f, 0.f, 0.f, 0.f);

    float c = 0.f;
    float xg_next = (tid < 16) ? g_xg[rowg] : 0.f;   // prefetch t=0
    __syncthreads();

    for (int t = 0; t < T_STEPS; ++t) {
        const float xgc = xg_next;
        if (tid < 16 && t + 1 < T_STEPS)
            xg_next = g_xg[(size_t)(t + 1) * G4H + rowg];   // prefetch next step

        // partial dot over this thread's 32 k-values (h broadcast from smem)
        float acc = 0.f;
        #pragma unroll
        for (int i = 0; i < 8; i++) {
            const float4 h = h4[kg * 9 + i];
            const float4 q = wv[i];
            acc = fmaf(q.x, h.x, acc);
            acc = fmaf(q.y, h.y, acc);
            acc = fmaf(q.z, h.z, acc);
            acc = fmaf(q.w, h.w, acc);
        }
        // combine the two k-halves within the warp
        acc += __shfl_xor_sync(0xffffffffu, acc, 16);
        if (l < 16) red[w * 16 + l] = acc;
        __syncthreads();

        if (tid < 16) {
            float g = xgc;
            #pragma unroll
            for (int ww = 0; ww < 8; ww++) g += red[ww * 16 + tid];
            gv[tid] = g;
        }
        __syncthreads();

        if (tid < 4) {  // pointwise LSTM update for hidden unit u0+tid
            const float ig = fsigm(gv[tid]);
            const float ff = fsigm(gv[4 + tid]);
            const float gg = ftanh(gv[8 + tid]);
            const float oo = fsigm(gv[12 + tid]);
            c = fmaf(ff, c, ig * gg);
            const float hn = oo * ftanh(c);
            g_hs[(size_t)t * H_DIM + u0 + tid] = hn;
            g_hbuf[((t + 1) & 1) * H_DIM + u0 + tid] = hn;
            __threadfence();  // order h writes before the stamp release
        }
        __syncthreads();

        if (tid == 0) {
            const unsigned v = (unsigned)(t + 1);
            asm volatile("st.global.release.gpu.u32 [%0], %1;"
                         :: "l"(&g_stamp[b * 8]), "r"(v) : "memory");
        }

        if (t + 1 < T_STEPS) {
            if (tid < 128) {
                // thread tid waits on producer CTA tid, then reads exactly its chunk
                const unsigned tgt = (unsigned)(t + 1);
                unsigned s;
                unsigned* sp = &g_stamp[tid * 8];
                do {
                    asm volatile("ld.global.acquire.gpu.u32 %0, [%1];"
                                 : "=r"(s) : "l"(sp) : "memory");
                } while (s < tgt);
                const float* hp = &g_hbuf[((t + 1) & 1) * H_DIM + tid * 4];
                float4 hv;
                asm volatile("ld.global.cg.v4.f32 {%0,%1,%2,%3}, [%4];"
                             : "=f"(hv.x), "=f"(hv.y), "=f"(hv.z), "=f"(hv.w)
                             : "l"(hp) : "memory");
                h4[(tid >> 3) * 9 + (tid & 7)] = hv;
            }
            __syncthreads();
        }
    }
}

// ---------------------------------------------------------------------------
// Kernel C: out = log_softmax(hs @ W_out^T + b_out)
// CTA = 8 t-rows; thread tid handles col tid (thread 0 also col 256).
// ---------------------------------------------------------------------------
__global__ void __launch_bounds__(256) out_kernel(
    const float* __restrict__ W_out, const float* __restrict__ b_out,
    float* __restrict__ out)
{
    __shared__ float hsm[8 * 512];
    __shared__ float red[256];
    const int tid = threadIdx.x;
    const int t0  = blockIdx.x * 8;

    for (int idx = tid; idx < 8 * 512; idx += 256)
        hsm[idx] = g_hs[(size_t)t0 * H_DIM + idx];
    __syncthreads();

    float acc[8], acc2[8];
    #pragma unroll
    for (int r = 0; r < 8; r++) { acc[r] = 0.f; acc2[r] = 0.f; }

    const float4* wr = reinterpret_cast<const float4*>(W_out + (size_t)tid * H_DIM);
    for (int kk = 0; kk < 128; kk++) {
        const float4 w4 = __ldg(wr + kk);
        #pragma unroll
        for (int rr = 0; rr < 8; rr++) {
            const float4 hv = *reinterpret_cast<const float4*>(&hsm[rr * 512 + kk * 4]);
            float a = acc[rr];
            a = fmaf(w4.x, hv.x, a);
            a = fmaf(w4.y, hv.y, a);
            a = fmaf(w4.z, hv.z, a);
            a = fmaf(w4.w, hv.w, a);
            acc[rr] = a;
        }
    }
    if (tid == 0) {  // column 256
        const float4* wr2 = reinterpret_cast<const float4*>(W_out + (size_t)256 * H_DIM);
        for (int kk = 0; kk < 128; kk++) {
            const float4 w4 = __ldg(wr2 + kk);
            #pragma unroll
            for (int rr = 0; rr < 8; rr++) {
                const float4 hv = *reinterpret_cast<const float4*>(&hsm[rr * 512 + kk * 4]);
                float a = acc2[rr];
                a = fmaf(w4.x, hv.x, a);
                a = fmaf(w4.y, hv.y, a);
                a = fmaf(w4.z, hv.z, a);
                a = fmaf(w4.w, hv.w, a);
                acc2[rr] = a;
            }
        }
    }

    const float bias  = __ldg(b_out + tid);
    const float bias2 = __ldg(b_out + 256);

    for (int r = 0; r < 8; r++) {
        const float z  = acc[r] + bias;
        const float z2 = acc2[r] + bias2;          // meaningful only for tid==0
        float m = (tid == 0) ? fmaxf(z, z2) : z;

        red[tid] = m; __syncthreads();
        for (int s = 128; s > 0; s >>= 1) {
            if (tid < s) red[tid] = fmaxf(red[tid], red[tid + s]);
            __syncthreads();
        }
        const float mx = red[0]; __syncthreads();

        float e = __expf(z - mx);
        if (tid == 0) e += __expf(z2 - mx);
        red[tid] = e; __syncthreads();
        for (int s = 128; s > 0; s >>= 1) {
            if (tid < s) red[tid] += red[tid + s];
            __syncthreads();
        }
        const float lse = logf(red[0]); __syncthreads();

        out[(size_t)(t0 + r) * O_DIM + tid] = z - mx - lse;
        if (tid == 0) out[(size_t)(t0 + r) * O_DIM + 256] = z2 - mx - lse;
    }
}

// ---------------------------------------------------------------------------
// kernel_launch: init -> input GEMM -> recurrence -> output GEMM+softmax
// ---------------------------------------------------------------------------
extern "C" void kernel_launch(void* const* d_in, const int* in_sizes, int n_in,
                              void* d_out, int out_size)
{
    const float* stft  = (const float*)d_in[0];
    const float* W_ih  = (const float*)d_in[1];
    const float* W_hh  = (const float*)d_in[2];
    const float* b_ih  = (const float*)d_in[3];
    const float* b_hh  = (const float*)d_in[4];
    const float* W_out = (const float*)d_in[5];
    const float* b_out = (const float*)d_in[6];
    float* out = (float*)d_out;

    init_kernel<<<1, 256>>>();
    xgate_gemm<<<T_STEPS / 16, 256>>>(stft, W_ih, b_ih, b_hh);
    lstm_rec<<<REC_CTAS, 256>>>(W_hh);
    out_kernel<<<T_STEPS / 8, 256>>>(W_out, b_out, out);
}

// round 3
// speedup vs baseline: 2.1351x; 2.1351x over previous
#include <cuda_runtime.h>
#include <cuda_bf16.h>
#include <math.h>

// Problem constants
#define T_STEPS 16384
#define D_IN    257
#define H_DIM   512
#define G4H     2048   // 4*H
#define O_DIM   257
#define REC_CTAS 128   // recurrence CTAs; each owns 4 hidden units (16 gate rows)
#define NREP    8      // replicas of the h-exchange buffer (spread L2 slices)

// Scratch (static __device__ arrays — no allocation allowed)
__device__ float    g_xg[(size_t)T_STEPS * G4H];   // 128 MB: precomputed input gates + biases
__device__ float    g_hs[(size_t)T_STEPS * H_DIM]; // 32 MB: h per timestep
// Tagged h exchange: [replica][parity][unit] -> (step_tag<<32)|float_bits
__device__ unsigned long long g_hx[NREP * 2 * H_DIM];

// ---------------------------------------------------------------------------
// init: reset exchange tags each launch (tags are monotonic within a launch)
// ---------------------------------------------------------------------------
__global__ void init_kernel() {
    const int idx = blockIdx.x * 256 + threadIdx.x;
    const int n = NREP * 2 * H_DIM;
    for (int i = idx; i < n; i += gridDim.x * 256) g_hx[i] = 0ull;
}

// ---------------------------------------------------------------------------
// Kernel A: x_gates[T, 4H] = stft @ W_ih^T + (b_ih + b_hh)
// ---------------------------------------------------------------------------
__global__ void __launch_bounds__(256) xgate_gemm(
    const float* __restrict__ stft, const float* __restrict__ W_ih,
    const float* __restrict__ b_ih, const float* __restrict__ b_hh)
{
    __shared__ float s_sh[16 * 260];  // row stride 260 (mult of 4 for float4)
    const int tid = threadIdx.x;
    const int t0  = blockIdx.x * 16;

    for (int r = 0; r < 16; r++)
        for (int d = tid; d < D_IN; d += 256)
            s_sh[r * 260 + d] = stft[(size_t)(t0 + r) * D_IN + d];
    __syncthreads();

    for (int cg = 0; cg < 8; cg++) {
        const int c = cg * 256 + tid;                  // 0..2047
        const float* wrow = W_ih + (size_t)c * D_IN;
        float acc[16];
        #pragma unroll
        for (int r = 0; r < 16; r++) acc[r] = 0.f;

        for (int dd = 0; dd < 64; dd++) {              // 64*4 = 256 of 257
            const float w0 = __ldg(wrow + dd * 4 + 0);
            const float w1 = __ldg(wrow + dd * 4 + 1);
            const float w2 = __ldg(wrow + dd * 4 + 2);
            const float w3 = __ldg(wrow + dd * 4 + 3);
            #pragma unroll
            for (int r = 0; r < 16; r++) {
                const float4 s4 = *reinterpret_cast<const float4*>(&s_sh[r * 260 + dd * 4]);
                float a = acc[r];
                a = fmaf(w0, s4.x, a);
                a = fmaf(w1, s4.y, a);
                a = fmaf(w2, s4.z, a);
                a = fmaf(w3, s4.w, a);
                acc[r] = a;
            }
        }
        const float wl = __ldg(wrow + 256);            // remainder d = 256
        #pragma unroll
        for (int r = 0; r < 16; r++) acc[r] = fmaf(wl, s_sh[r * 260 + 256], acc[r]);

        const float bias = __ldg(b_ih + c) + __ldg(b_hh + c);
        #pragma unroll
        for (int r = 0; r < 16; r++)
            g_xg[(size_t)(t0 + r) * G4H + c] = acc[r] + bias;
    }
}

// ---------------------------------------------------------------------------
// Kernel B: sequential LSTM recurrence, persistent grid of 128 CTAs.
// CTA b owns hidden units u0=4b..4b+3 -> 16 gate rows (i,f,g,o x 4 units).
// W_hh slice lives in registers. h exchanged via L2 as (tag,h) 64-bit words.
// All exchange accesses are MORALLY STRONG (relaxed atomics, gpu scope) so
// 8-byte single-copy atomicity is guaranteed: tag-valid => value-valid.
// NREP replicas spread LTS slice load; parity double-buffer per step.
// ---------------------------------------------------------------------------
__device__ __forceinline__ float fsigm(float x) { return 1.0f / (1.0f + __expf(-x)); }
__device__ __forceinline__ float ftanh(float x) { return 2.0f / (1.0f + __expf(-2.0f * x)) - 1.0f; }

__global__ void __launch_bounds__(256) lstm_rec(const float* __restrict__ W_hh)
{
    __shared__ float4 h4[144];   // padded: index kg*9 + i (conflict-free)
    __shared__ float  red[128];  // per-warp row partials
    __shared__ float  gv[16];    // final gate preactivations

    const int tid = threadIdx.x;
    const int b   = blockIdx.x;
    const int w   = tid >> 5;
    const int l   = tid & 31;
    const int r   = l & 15;
    const int kh  = l >> 4;
    const int kg  = w * 2 + kh;          // 0..15, k range [kg*32, kg*32+32)
    const int u0  = b * 4;
    const int rowg = (r >> 2) * 512 + u0 + (r & 3);  // global gate row

    // weights for (rowg, k in [kg*32, kg*32+32)) in registers
    float4 wv[8];
    const float4* wp = reinterpret_cast<const float4*>(W_hh + (size_t)rowg * H_DIM + (size_t)kg * 32);
    #pragma unroll
    for (int i = 0; i < 8; i++) wv[i] = __ldg(wp + i);

    if (tid < 128) h4[(tid >> 3) * 9 + (tid & 7)] = make_float4(0.f, 0.f, 0.f, 0.f);

    // producer role: threads j<32 redundantly run the pointwise update for
    // unit u0+(j&3) (identical deterministic FP math), each writing replica j>>2
    float c = 0.f;
    const int pu  = tid & 3;          // producer unit index (tid<32)
    const int prep = tid >> 2;        // producer replica    (tid<32, 0..7)
    // consumer role: thread tid<128 polls the 4 tagged words of producer CTA `tid`
    const int crep = b & (NREP - 1);

    float xg_next = (tid < 16) ? g_xg[rowg] : 0.f;   // prefetch t=0
    __syncthreads();

    for (int t = 0; t < T_STEPS; ++t) {
        const float xgc = xg_next;
        if (tid < 16 && t + 1 < T_STEPS)
            xg_next = g_xg[(size_t)(t + 1) * G4H + rowg];   // prefetch next step

        // partial dot over this thread's 32 k-values (h broadcast from smem)
        float acc = 0.f;
        #pragma unroll
        for (int i = 0; i < 8; i++) {
            const float4 h = h4[kg * 9 + i];
            const float4 q = wv[i];
            acc = fmaf(q.x, h.x, acc);
            acc = fmaf(q.y, h.y, acc);
            acc = fmaf(q.z, h.z, acc);
            acc = fmaf(q.w, h.w, acc);
        }
        // combine the two k-halves within the warp
        acc += __shfl_xor_sync(0xffffffffu, acc, 16);
        if (l < 16) red[w * 16 + l] = acc;
        __syncthreads();

        if (tid < 16) {
            float g = xgc;
            #pragma unroll
            for (int ww = 0; ww < 8; ww++) g += red[ww * 16 + tid];
            gv[tid] = g;
        }
        __syncthreads();

        const int par = (t + 1) & 1;

        if (tid < 32) {  // pointwise LSTM update (replicated across 8 replicas)
            const float ig = fsigm(gv[pu]);
            const float ff = fsigm(gv[4 + pu]);
            const float gg = ftanh(gv[8 + pu]);
            const float oo = fsigm(gv[12 + pu]);
            c = fmaf(ff, c, ig * gg);
            const float hn = oo * ftanh(c);
            if (tid < 4) g_hs[(size_t)t * H_DIM + u0 + pu] = hn;
            const unsigned long long word =
                ((unsigned long long)(unsigned)(t + 1) << 32) | (unsigned long long)__float_as_uint(hn);
            unsigned long long* dst = &g_hx[((size_t)(prep * 2 + par)) * H_DIM + u0 + pu];
            // morally strong relaxed store: guaranteed 8B single-copy atomic
            asm volatile("st.global.relaxed.gpu.b64 [%0], %1;" :: "l"(dst), "l"(word) : "memory");
        }

        if (t + 1 < T_STEPS) {
            if (tid < 128) {
                // poll the 4 tagged words from producer CTA `tid` in our replica
                const unsigned tgt = (unsigned)(t + 1);
                unsigned long long* src =
                    &g_hx[((size_t)(crep * 2 + par)) * H_DIM + tid * 4];
                unsigned long long v0, v1, v2, v3;
                while (true) {
                    asm volatile("ld.global.relaxed.gpu.b64 %0, [%1];"
                                 : "=l"(v0) : "l"(src) : "memory");
                    asm volatile("ld.global.relaxed.gpu.b64 %0, [%1];"
                                 : "=l"(v1) : "l"(src + 1) : "memory");
                    asm volatile("ld.global.relaxed.gpu.b64 %0, [%1];"
                                 : "=l"(v2) : "l"(src + 2) : "memory");
                    asm volatile("ld.global.relaxed.gpu.b64 %0, [%1];"
                                 : "=l"(v3) : "l"(src + 3) : "memory");
                    if ((unsigned)(v0 >> 32) == tgt && (unsigned)(v1 >> 32) == tgt &&
                        (unsigned)(v2 >> 32) == tgt && (unsigned)(v3 >> 32) == tgt)
                        break;
                }
                float4 hv;
                hv.x = __uint_as_float((unsigned)v0);
                hv.y = __uint_as_float((unsigned)v1);
                hv.z = __uint_as_float((unsigned)v2);
                hv.w = __uint_as_float((unsigned)v3);
                h4[(tid >> 3) * 9 + (tid & 7)] = hv;
            }
            __syncthreads();
        }
    }
}

// ---------------------------------------------------------------------------
// Kernel C: out = log_softmax(hs @ W_out^T + b_out)
// ---------------------------------------------------------------------------
__global__ void __launch_bounds__(256) out_kernel(
    const float* __restrict__ W_out, const float* __restrict__ b_out,
    float* __restrict__ out)
{
    __shared__ float hsm[8 * 512];
    __shared__ float red[256];
    const int tid = threadIdx.x;
    const int t0  = blockIdx.x * 8;

    for (int idx = tid; idx < 8 * 512; idx += 256)
        hsm[idx] = g_hs[(size_t)t0 * H_DIM + idx];
    __syncthreads();

    float acc[8], acc2[8];
    #pragma unroll
    for (int r = 0; r < 8; r++) { acc[r] = 0.f; acc2[r] = 0.f; }

    const float4* wr = reinterpret_cast<const float4*>(W_out + (size_t)tid * H_DIM);
    for (int kk = 0; kk < 128; kk++) {
        const float4 w4 = __ldg(wr + kk);
        #pragma unroll
        for (int rr = 0; rr < 8; rr++) {
            const float4 hv = *reinterpret_cast<const float4*>(&hsm[rr * 512 + kk * 4]);
            float a = acc[rr];
            a = fmaf(w4.x, hv.x, a);
            a = fmaf(w4.y, hv.y, a);
            a = fmaf(w4.z, hv.z, a);
            a = fmaf(w4.w, hv.w, a);
            acc[rr] = a;
        }
    }
    if (tid == 0) {  // column 256
        const float4* wr2 = reinterpret_cast<const float4*>(W_out + (size_t)256 * H_DIM);
        for (int kk = 0; kk < 128; kk++) {
            const float4 w4 = __ldg(wr2 + kk);
            #pragma unroll
            for (int rr = 0; rr < 8; rr++) {
                const float4 hv = *reinterpret_cast<const float4*>(&hsm[rr * 512 + kk * 4]);
                float a = acc2[rr];
                a = fmaf(w4.x, hv.x, a);
                a = fmaf(w4.y, hv.y, a);
                a = fmaf(w4.z, hv.z, a);
                a = fmaf(w4.w, hv.w, a);
                acc2[rr] = a;
            }
        }
    }

    const float bias  = __ldg(b_out + tid);
    const float bias2 = __ldg(b_out + 256);

    for (int r = 0; r < 8; r++) {
        const float z  = acc[r] + bias;
        const float z2 = acc2[r] + bias2;          // meaningful only for tid==0
        float m = (tid == 0) ? fmaxf(z, z2) : z;

        red[tid] = m; __syncthreads();
        for (int s = 128; s > 0; s >>= 1) {
            if (tid < s) red[tid] = fmaxf(red[tid], red[tid + s]);
            __syncthreads();
        }
        const float mx = red[0]; __syncthreads();

        float e = __expf(z - mx);
        if (tid == 0) e += __expf(z2 - mx);
        red[tid] = e; __syncthreads();
        for (int s = 128; s > 0; s >>= 1) {
            if (tid < s) red[tid] += red[tid + s];
            __syncthreads();
        }
        const float lse = logf(red[0]); __syncthreads();

        out[(size_t)(t0 + r) * O_DIM + tid] = z - mx - lse;
        if (tid == 0) out[(size_t)(t0 + r) * O_DIM + 256] = z2 - mx - lse;
    }
}

// ---------------------------------------------------------------------------
// kernel_launch: init -> input GEMM -> recurrence -> output GEMM+softmax
// ---------------------------------------------------------------------------
extern "C" void kernel_launch(void* const* d_in, const int* in_sizes, int n_in,
                              void* d_out, int out_size)
{
    const float* stft  = (const float*)d_in[0];
    const float* W_ih  = (const float*)d_in[1];
    const float* W_hh  = (const float*)d_in[2];
    const float* b_ih  = (const float*)d_in[3];
    const float* b_hh  = (const float*)d_in[4];
    const float* W_out = (const float*)d_in[5];
    const float* b_out = (const float*)d_in[6];
    float* out = (float*)d_out;

    init_kernel<<<8, 256>>>();
    xgate_gemm<<<T_STEPS / 16, 256>>>(stft, W_ih, b_ih, b_hh);
    lstm_rec<<<REC_CTAS, 256>>>(W_hh);
    out_kernel<<<T_STEPS / 8, 256>>>(W_out, b_out, out);
}